// round 4
// baseline (speedup 1.0000x reference)
#include <cuda_runtime.h>
#include <cstdint>

// ---------------- problem dims ----------------
#define MTOK 32768
#define DD   1024
#define NQKV 3072
#define NT   32            // K=1024 / BK=32 k-tiles

// ---------------- scratch (device globals; no allocation allowed) ----------------
__device__ float g_xr  [(size_t)MTOK * DD];      // tf32-rounded x
__device__ float g_wqkv[3 * DD * DD];            // packed wq|wk|wv (tf32)
__device__ float g_wor [DD * DD];                // tf32-rounded wo
__device__ float g_qkv [(size_t)MTOK * NQKV];    // packed q|k|v per token
__device__ float g_ctx [(size_t)MTOK * DD];      // tf32-rounded context

// ---------------- helpers ----------------
__device__ __forceinline__ float round_tf32(float x) {
    uint32_t r;
    asm("cvt.rna.tf32.f32 %0, %1;" : "=r"(r) : "f"(x));
    return __uint_as_float(r);
}

__global__ void round_x_kernel(float4* __restrict__ dst,
                               const float4* __restrict__ src, int n4) {
    int i = blockIdx.x * blockDim.x + threadIdx.x;
    if (i < n4) {
        float4 a = src[i];
        a.x = round_tf32(a.x); a.y = round_tf32(a.y);
        a.z = round_tf32(a.z); a.w = round_tf32(a.w);
        dst[i] = a;
    }
}

// pack + round wq|wk|wv into one buffer (each matrix = 2^18 float4s)
__global__ void round_wqkv_kernel(float4* __restrict__ dst,
                                  const float4* __restrict__ w0,
                                  const float4* __restrict__ w1,
                                  const float4* __restrict__ w2) {
    int i = blockIdx.x * blockDim.x + threadIdx.x;   // < 3*262144
    const float4* s = (i < 262144) ? w0 : (i < 524288 ? w1 : w2);
    float4 a = s[i & 262143];
    a.x = round_tf32(a.x); a.y = round_tf32(a.y);
    a.z = round_tf32(a.z); a.w = round_tf32(a.w);
    dst[i] = a;
}

// ---------------- TF32 GEMM (mma.sync): C[128,128] tile = A @ W^T + bias ----------------
// 3-stage cp.async pipeline, XOR-swizzled 128B-row smem tiles, 8 warps (2x4).
#define STAGE_B 32768            // A tile 16KB + B tile 16KB
#define SWF(off) ((((off) ^ (((off) >> 3) & 0x70u))) >> 2)

__device__ __forceinline__ void cp_async16(uint32_t smem, const void* gmem) {
    asm volatile("cp.async.cg.shared.global [%0], [%1], 16;\n" :: "r"(smem), "l"(gmem));
}

__global__ __launch_bounds__(256, 2)
void gemm_tf32(const float* __restrict__ A, const float* __restrict__ W,
               const float* __restrict__ b0, const float* __restrict__ b1,
               const float* __restrict__ b2, float* __restrict__ C, int ldc)
{
    extern __shared__ float sm[];
    uint32_t smem_u = (uint32_t)__cvta_generic_to_shared(sm);
    uint32_t tiles_u = (smem_u + 1023u) & ~1023u;          // 128B+ aligned tile base
    const int tbase_f = (int)((tiles_u - smem_u) >> 2);    // float offset of tile area

    const int tid  = threadIdx.x;
    const int warp = tid >> 5, lane = tid & 31;
    const int wm   = warp >> 2, wn = warp & 3;             // 2 x 4 warp grid
    const int K    = DD;
    const float* Ag = A + (size_t)blockIdx.y * 128 * K;
    const float* Wg = W + (size_t)blockIdx.x * 128 * K;

    // ---- stage loader: 2048 x 16B chunks (A rows then B rows), swizzled dst
    auto load_stage = [&](int kt, int s) {
        uint32_t st = tiles_u + (uint32_t)s * STAGE_B;
        #pragma unroll
        for (int i = 0; i < 8; i++) {
            int e    = tid + i * 256;          // 0..2047
            int half = e >> 10;                // 0=A, 1=B (uniform per i)
            int r    = (e >> 3) & 127;
            int c4   = e & 7;
            uint32_t off = (uint32_t)(r * 128 + c4 * 16);
            uint32_t dst = st + (uint32_t)half * 16384u + (off ^ ((off >> 3) & 0x70u));
            const float* src = (half ? Wg : Ag) + (size_t)r * K + kt * 32 + c4 * 4;
            cp_async16(dst, src);
        }
        asm volatile("cp.async.commit_group;");
    };

    load_stage(0, 0);
    load_stage(1, 1);

    float acc[4][4][4];
    #pragma unroll
    for (int a = 0; a < 4; a++)
        #pragma unroll
        for (int b = 0; b < 4; b++)
            #pragma unroll
            for (int c = 0; c < 4; c++) acc[a][b][c] = 0.f;

    const int lt = lane & 3;
    const int lr = lane >> 2;

    for (int kt = 0; kt < NT; kt++) {
        if (kt + 1 < NT) asm volatile("cp.async.wait_group 1;");
        else             asm volatile("cp.async.wait_group 0;");
        __syncthreads();
        if (kt + 2 < NT) load_stage(kt + 2, (kt + 2) % 3);

        const int aB = tbase_f + (kt % 3) * (STAGE_B >> 2);   // A tile float base
        const int bB = aB + 4096;                              // B tile float base

        #pragma unroll
        for (int kk = 0; kk < 4; kk++) {
            const uint32_t cb = (uint32_t)((kk * 8 + lt) * 4);  // byte col of k
            float af[4][4], bf[4][2];
            #pragma unroll
            for (int mf = 0; mf < 4; mf++) {
                uint32_t r0 = (uint32_t)((wm * 64 + lr + mf * 16) * 128);
                uint32_t r1 = r0 + 8 * 128;
                af[mf][0] = sm[aB + SWF(r0 + cb)];
                af[mf][1] = sm[aB + SWF(r1 + cb)];
                af[mf][2] = sm[aB + SWF(r0 + cb + 16)];
                af[mf][3] = sm[aB + SWF(r1 + cb + 16)];
            }
            #pragma unroll
            for (int nf = 0; nf < 4; nf++) {
                uint32_t rb = (uint32_t)((wn * 32 + lr + nf * 8) * 128);
                bf[nf][0] = sm[bB + SWF(rb + cb)];
                bf[nf][1] = sm[bB + SWF(rb + cb + 16)];
            }
            #pragma unroll
            for (int mf = 0; mf < 4; mf++)
                #pragma unroll
                for (int nf = 0; nf < 4; nf++)
                    asm volatile(
                        "mma.sync.aligned.m16n8k8.row.col.f32.tf32.tf32.f32 "
                        "{%0,%1,%2,%3}, {%4,%5,%6,%7}, {%8,%9}, {%0,%1,%2,%3};"
                        : "+f"(acc[mf][nf][0]), "+f"(acc[mf][nf][1]),
                          "+f"(acc[mf][nf][2]), "+f"(acc[mf][nf][3])
                        : "r"(__float_as_uint(af[mf][0])), "r"(__float_as_uint(af[mf][1])),
                          "r"(__float_as_uint(af[mf][2])), "r"(__float_as_uint(af[mf][3])),
                          "r"(__float_as_uint(bf[nf][0])), "r"(__float_as_uint(bf[nf][1])));
        }
        __syncthreads();
    }

    // ---- epilogue: bias (region-selected) + float2 stores
    const int colbase = blockIdx.x * 128;
    const float* bias = (colbase < 1024) ? b0 : (colbase < 2048 ? b1 : b2);
    const int bofs    = colbase & 1023;
    const int crow0   = blockIdx.y * 128 + wm * 64 + lr;
    const int ccl     = wn * 32 + lt * 2;                 // local col in tile
    #pragma unroll
    for (int mf = 0; mf < 4; mf++) {
        #pragma unroll
        for (int nf = 0; nf < 4; nf++) {
            int r  = crow0 + mf * 16;
            int cl = ccl + nf * 8;
            float bb0 = __ldg(bias + bofs + cl), bb1 = __ldg(bias + bofs + cl + 1);
            *(float2*)&C[(size_t)r * ldc + colbase + cl] =
                make_float2(acc[mf][nf][0] + bb0, acc[mf][nf][1] + bb1);
            *(float2*)&C[(size_t)(r + 8) * ldc + colbase + cl] =
                make_float2(acc[mf][nf][2] + bb0, acc[mf][nf][3] + bb1);
        }
    }
}

// ---------------- per-token attention (softmax over HEAD axis) ----------------
__global__ void attn_kernel(const float* __restrict__ QKV, float* __restrict__ CTX)
{
    __shared__ float sq[16][68], sk[16][68], sv[16][68], sp[16][17];
    const int t   = blockIdx.x;
    const int tid = threadIdx.x;
    const int h   = tid >> 4;
    const int g   = tid & 15;

    const float4* r4 = (const float4*)(QKV + (size_t)t * NQKV);
    *(float4*)&sq[h][g * 4] = r4[tid];
    *(float4*)&sk[h][g * 4] = r4[256 + tid];
    *(float4*)&sv[h][g * 4] = r4[512 + tid];
    __syncthreads();

    float s = 0.f;
    #pragma unroll
    for (int d = 0; d < 16; d++) {
        float4 qa = *(const float4*)&sq[h][d * 4];
        float4 ka = *(const float4*)&sk[g][d * 4];
        s += qa.x * ka.x + qa.y * ka.y + qa.z * ka.z + qa.w * ka.w;
    }
    s *= 0.125f;

    float m = s;
    #pragma unroll
    for (int o = 8; o; o >>= 1) m = fmaxf(m, __shfl_xor_sync(0xffffffffu, m, o));
    float e = __expf(s - m);
    float sum = e;
    #pragma unroll
    for (int o = 8; o; o >>= 1) sum += __shfl_xor_sync(0xffffffffu, sum, o);
    sp[h][g] = e / sum;
    __syncthreads();

    float4 acc = make_float4(0.f, 0.f, 0.f, 0.f);
    #pragma unroll
    for (int gg = 0; gg < 16; gg++) {
        float p   = sp[h][gg];
        float4 va = *(const float4*)&sv[gg][g * 4];
        acc.x += p * va.x; acc.y += p * va.y;
        acc.z += p * va.z; acc.w += p * va.w;
    }
    acc.x = round_tf32(acc.x); acc.y = round_tf32(acc.y);
    acc.z = round_tf32(acc.z); acc.w = round_tf32(acc.w);
    ((float4*)(CTX + (size_t)t * DD))[tid] = acc;
}

// ---------------- launch (6 launches; #6 = O-GEMM for ncu -s5 -c1) ----------------
extern "C" void kernel_launch(void* const* d_in, const int* in_sizes, int n_in,
                              void* d_out, int out_size)
{
    const float* x  = (const float*)d_in[0];
    const float* wq = (const float*)d_in[1];
    const float* bq = (const float*)d_in[2];
    const float* wk = (const float*)d_in[3];
    const float* bk = (const float*)d_in[4];
    const float* wv = (const float*)d_in[5];
    const float* bv = (const float*)d_in[6];
    const float* wo = (const float*)d_in[7];
    const float* bo = (const float*)d_in[8];
    float* out = (float*)d_out;

    float *p_xr, *p_wqkv, *p_wor, *p_qkv, *p_ctx;
    cudaGetSymbolAddress((void**)&p_xr,   g_xr);
    cudaGetSymbolAddress((void**)&p_wqkv, g_wqkv);
    cudaGetSymbolAddress((void**)&p_wor,  g_wor);
    cudaGetSymbolAddress((void**)&p_qkv,  g_qkv);
    cudaGetSymbolAddress((void**)&p_ctx,  g_ctx);

    const int smem = 3 * STAGE_B + 1024;   // 99328 B (3 stages + align slack)
    cudaFuncSetAttribute(gemm_tf32, cudaFuncAttributeMaxDynamicSharedMemorySize, smem);

    // 1) round x
    {
        int n4 = (int)((size_t)MTOK * DD / 4);
        round_x_kernel<<<(n4 + 255) / 256, 256>>>((float4*)p_xr, (const float4*)x, n4);
    }
    // 2) round+pack wq|wk|wv
    round_wqkv_kernel<<<(3 * 262144 + 255) / 256, 256>>>(
        (float4*)p_wqkv, (const float4*)wq, (const float4*)wk, (const float4*)wv);
    // 3) round wo
    {
        int w4 = DD * DD / 4;
        round_x_kernel<<<(w4 + 255) / 256, 256>>>((float4*)p_wor, (const float4*)wo, w4);
    }

    // 4) fused QKV projection: [32768,1024] @ [3072,1024]^T
    gemm_tf32<<<dim3(NQKV / 128, MTOK / 128), 256, smem>>>(
        p_xr, p_wqkv, bq, bk, bv, p_qkv, NQKV);

    // 5) per-token head-softmax attention
    attn_kernel<<<MTOK, 256>>>(p_qkv, p_ctx);

    // 6) output projection
    gemm_tf32<<<dim3(DD / 128, MTOK / 128), 256, smem>>>(
        p_ctx, p_wor, bo, bo, bo, out, DD);
}

// round 5
// speedup vs baseline: 1.1599x; 1.1599x over previous
#include <cuda_runtime.h>
#include <cstdint>

// ---------------- problem dims ----------------
#define MTOK 32768
#define DD   1024
#define NQKV 3072
#define NT   32            // K=1024 / BK=32 k-tiles

// ---------------- scratch (device globals; no allocation allowed) ----------------
__device__ float g_xr  [(size_t)MTOK * DD];      // tf32-rounded x
__device__ float g_wqkv[3 * DD * DD];            // packed wq|wk|wv (tf32)
__device__ float g_wor [DD * DD];                // tf32-rounded wo
__device__ float g_qkv [(size_t)MTOK * NQKV];    // packed q|k|v per token
__device__ float g_ctx [(size_t)MTOK * DD];      // tf32-rounded context

// ---------------- helpers ----------------
__device__ __forceinline__ float round_tf32(float x) {
    uint32_t r;
    asm("cvt.rna.tf32.f32 %0, %1;" : "=r"(r) : "f"(x));
    return __uint_as_float(r);
}

__global__ void round_x_kernel(float4* __restrict__ dst,
                               const float4* __restrict__ src, int n4) {
    int i = blockIdx.x * blockDim.x + threadIdx.x;
    if (i < n4) {
        float4 a = src[i];
        a.x = round_tf32(a.x); a.y = round_tf32(a.y);
        a.z = round_tf32(a.z); a.w = round_tf32(a.w);
        dst[i] = a;
    }
}

__global__ void round_wqkv_kernel(float4* __restrict__ dst,
                                  const float4* __restrict__ w0,
                                  const float4* __restrict__ w1,
                                  const float4* __restrict__ w2) {
    int i = blockIdx.x * blockDim.x + threadIdx.x;   // < 3*262144
    const float4* s = (i < 262144) ? w0 : (i < 524288 ? w1 : w2);
    float4 a = s[i & 262143];
    a.x = round_tf32(a.x); a.y = round_tf32(a.y);
    a.z = round_tf32(a.z); a.w = round_tf32(a.w);
    dst[i] = a;
}

// ---------------- TF32 GEMM (mma.sync): C tile 128x128 = A @ W^T + bias ----------------
// Padded-stride smem (LDT=36 floats = 144B rows), 3-stage cp.async ring,
// single __syncthreads per k-iter, 8 warps (2x4), warp tile 64x32.
#define LDT 36
#define STAGE_F (2 * 128 * LDT)          // floats per stage (A+B) = 9216
#define STAGE_BYTES (STAGE_F * 4)        // 36864

__device__ __forceinline__ void cp_async16(uint32_t smem, const void* gmem) {
    asm volatile("cp.async.cg.shared.global [%0], [%1], 16;\n" :: "r"(smem), "l"(gmem));
}

__global__ __launch_bounds__(256, 2)
void gemm_tf32(const float* __restrict__ A, const float* __restrict__ W,
               const float* __restrict__ b0, const float* __restrict__ b1,
               const float* __restrict__ b2, float* __restrict__ C, int ldc)
{
    extern __shared__ float sm[];
    uint32_t sm_u = (uint32_t)__cvta_generic_to_shared(sm);

    const int tid  = threadIdx.x;
    const int warp = tid >> 5, lane = tid & 31;
    const int wm   = warp >> 2, wn = warp & 3;     // 2 x 4 warp grid
    const int lt   = lane & 3,  lr = lane >> 2;
    const int K    = DD;

    // ---- loader state: fixed per thread ----
    const int rowt = tid >> 3;                     // 0..31
    const int c4   = tid & 7;                      // 16B chunk in row
    const float* aBase = A + (size_t)blockIdx.y * 128 * K + (size_t)rowt * K + c4 * 4;
    const float* bBase = W + (size_t)blockIdx.x * 128 * K + (size_t)rowt * K + c4 * 4;
    const uint32_t dstoff = (uint32_t)(rowt * 144 + c4 * 16);

    auto load_stage = [&](int kt, int s) {
        uint32_t st = sm_u + (uint32_t)s * STAGE_BYTES;
        const float* ap = aBase + kt * 32;
        const float* bp = bBase + kt * 32;
        #pragma unroll
        for (int i = 0; i < 4; i++) {
            cp_async16(st + dstoff + (uint32_t)i * 4608u,            ap + (size_t)i * 32 * K);
            cp_async16(st + 18432u + dstoff + (uint32_t)i * 4608u,   bp + (size_t)i * 32 * K);
        }
        asm volatile("cp.async.commit_group;");
    };

    load_stage(0, 0);
    load_stage(1, 1);

    float acc[4][4][4];
    #pragma unroll
    for (int a = 0; a < 4; a++)
        #pragma unroll
        for (int b = 0; b < 4; b++)
            #pragma unroll
            for (int c = 0; c < 4; c++) acc[a][b][c] = 0.f;

    for (int kt = 0; kt < NT; kt++) {
        if (kt + 1 < NT) asm volatile("cp.async.wait_group 1;");
        else             asm volatile("cp.async.wait_group 0;");
        __syncthreads();
        if (kt + 2 < NT) load_stage(kt + 2, (kt + 2) % 3);

        const float* As = sm + (kt % 3) * STAGE_F;
        const float* Ws = As + 128 * LDT;

        #pragma unroll
        for (int kk = 0; kk < 4; kk++) {
            float af[4][4], bf[4][2];
            const int ar = wm * 64 + lr;
            const int ac = kk * 8 + lt;
            #pragma unroll
            for (int mf = 0; mf < 4; mf++) {
                af[mf][0] = As[(ar + mf * 16    ) * LDT + ac    ];
                af[mf][1] = As[(ar + mf * 16 + 8) * LDT + ac    ];
                af[mf][2] = As[(ar + mf * 16    ) * LDT + ac + 4];
                af[mf][3] = As[(ar + mf * 16 + 8) * LDT + ac + 4];
            }
            const int br = wn * 32 + lr;
            #pragma unroll
            for (int nf = 0; nf < 4; nf++) {
                bf[nf][0] = Ws[(br + nf * 8) * LDT + ac    ];
                bf[nf][1] = Ws[(br + nf * 8) * LDT + ac + 4];
            }
            #pragma unroll
            for (int mf = 0; mf < 4; mf++)
                #pragma unroll
                for (int nf = 0; nf < 4; nf++)
                    asm volatile(
                        "mma.sync.aligned.m16n8k8.row.col.f32.tf32.tf32.f32 "
                        "{%0,%1,%2,%3}, {%4,%5,%6,%7}, {%8,%9}, {%0,%1,%2,%3};"
                        : "+f"(acc[mf][nf][0]), "+f"(acc[mf][nf][1]),
                          "+f"(acc[mf][nf][2]), "+f"(acc[mf][nf][3])
                        : "r"(__float_as_uint(af[mf][0])), "r"(__float_as_uint(af[mf][1])),
                          "r"(__float_as_uint(af[mf][2])), "r"(__float_as_uint(af[mf][3])),
                          "r"(__float_as_uint(bf[nf][0])), "r"(__float_as_uint(bf[nf][1])));
        }
        __syncthreads();
    }

    // ---- epilogue: region-selected bias + float2 stores ----
    const int colbase = blockIdx.x * 128;
    const float* bias = (colbase < 1024) ? b0 : (colbase < 2048 ? b1 : b2);
    const int bofs    = colbase & 1023;
    const int crow0   = blockIdx.y * 128 + wm * 64 + lr;
    const int ccl     = wn * 32 + lt * 2;
    #pragma unroll
    for (int mf = 0; mf < 4; mf++) {
        #pragma unroll
        for (int nf = 0; nf < 4; nf++) {
            int r  = crow0 + mf * 16;
            int cl = ccl + nf * 8;
            float bb0 = __ldg(bias + bofs + cl), bb1 = __ldg(bias + bofs + cl + 1);
            *(float2*)&C[(size_t)r * ldc + colbase + cl] =
                make_float2(acc[mf][nf][0] + bb0, acc[mf][nf][1] + bb1);
            *(float2*)&C[(size_t)(r + 8) * ldc + colbase + cl] =
                make_float2(acc[mf][nf][2] + bb0, acc[mf][nf][3] + bb1);
        }
    }
}

// ---------------- per-token attention (softmax over HEAD axis) ----------------
__global__ void attn_kernel(const float* __restrict__ QKV, float* __restrict__ CTX)
{
    __shared__ float sq[16][68], sk[16][68], sv[16][68], sp[16][17];
    const int t   = blockIdx.x;
    const int tid = threadIdx.x;
    const int h   = tid >> 4;
    const int g   = tid & 15;

    const float4* r4 = (const float4*)(QKV + (size_t)t * NQKV);
    *(float4*)&sq[h][g * 4] = r4[tid];
    *(float4*)&sk[h][g * 4] = r4[256 + tid];
    *(float4*)&sv[h][g * 4] = r4[512 + tid];
    __syncthreads();

    float s = 0.f;
    #pragma unroll
    for (int d = 0; d < 16; d++) {
        float4 qa = *(const float4*)&sq[h][d * 4];
        float4 ka = *(const float4*)&sk[g][d * 4];
        s += qa.x * ka.x + qa.y * ka.y + qa.z * ka.z + qa.w * ka.w;
    }
    s *= 0.125f;

    float m = s;
    #pragma unroll
    for (int o = 8; o; o >>= 1) m = fmaxf(m, __shfl_xor_sync(0xffffffffu, m, o));
    float e = __expf(s - m);
    float sum = e;
    #pragma unroll
    for (int o = 8; o; o >>= 1) sum += __shfl_xor_sync(0xffffffffu, sum, o);
    sp[h][g] = e / sum;
    __syncthreads();

    float4 acc = make_float4(0.f, 0.f, 0.f, 0.f);
    #pragma unroll
    for (int gg = 0; gg < 16; gg++) {
        float p   = sp[h][gg];
        float4 va = *(const float4*)&sv[gg][g * 4];
        acc.x += p * va.x; acc.y += p * va.y;
        acc.z += p * va.z; acc.w += p * va.w;
    }
    acc.x = round_tf32(acc.x); acc.y = round_tf32(acc.y);
    acc.z = round_tf32(acc.z); acc.w = round_tf32(acc.w);
    ((float4*)(CTX + (size_t)t * DD))[tid] = acc;
}

// ---------------- launch (6 launches; #6 = O-GEMM for ncu -s5 -c1) ----------------
extern "C" void kernel_launch(void* const* d_in, const int* in_sizes, int n_in,
                              void* d_out, int out_size)
{
    const float* x  = (const float*)d_in[0];
    const float* wq = (const float*)d_in[1];
    const float* bq = (const float*)d_in[2];
    const float* wk = (const float*)d_in[3];
    const float* bk = (const float*)d_in[4];
    const float* wv = (const float*)d_in[5];
    const float* bv = (const float*)d_in[6];
    const float* wo = (const float*)d_in[7];
    const float* bo = (const float*)d_in[8];
    float* out = (float*)d_out;

    float *p_xr, *p_wqkv, *p_wor, *p_qkv, *p_ctx;
    cudaGetSymbolAddress((void**)&p_xr,   g_xr);
    cudaGetSymbolAddress((void**)&p_wqkv, g_wqkv);
    cudaGetSymbolAddress((void**)&p_wor,  g_wor);
    cudaGetSymbolAddress((void**)&p_qkv,  g_qkv);
    cudaGetSymbolAddress((void**)&p_ctx,  g_ctx);

    const int smem = 3 * STAGE_BYTES;   // 110592 B
    cudaFuncSetAttribute(gemm_tf32, cudaFuncAttributeMaxDynamicSharedMemorySize, smem);

    // 1) round x
    {
        int n4 = (int)((size_t)MTOK * DD / 4);
        round_x_kernel<<<(n4 + 255) / 256, 256>>>((float4*)p_xr, (const float4*)x, n4);
    }
    // 2) round+pack wq|wk|wv
    round_wqkv_kernel<<<(3 * 262144 + 255) / 256, 256>>>(
        (float4*)p_wqkv, (const float4*)wq, (const float4*)wk, (const float4*)wv);
    // 3) round wo
    {
        int w4 = DD * DD / 4;
        round_x_kernel<<<(w4 + 255) / 256, 256>>>((float4*)p_wor, (const float4*)wo, w4);
    }

    // 4) fused QKV projection: [32768,1024] @ [3072,1024]^T
    gemm_tf32<<<dim3(NQKV / 128, MTOK / 128), 256, smem>>>(
        p_xr, p_wqkv, bq, bk, bv, p_qkv, NQKV);

    // 5) per-token head-softmax attention
    attn_kernel<<<MTOK, 256>>>(p_qkv, p_ctx);

    // 6) output projection
    gemm_tf32<<<dim3(DD / 128, MTOK / 128), 256, smem>>>(
        p_ctx, p_wor, bo, bo, bo, out, DD);
}